// round 1
// baseline (speedup 1.0000x reference)
#include <cuda_runtime.h>
#include <cuda_bf16.h>
#include <cstdint>

// Problem constants
#define A_NUM   3
#define S_DIM   32
#define H_DIM   128
#define W_DIM   128
#define SHW     (S_DIM * H_DIM * W_DIM)      // 524288
#define N_SC    (A_NUM * SHW)                // 1572864
#define PRE_TOPN  2000
#define POST_TOPN 300
#define NMS_T     0.7f
#define MASK_COLS 32                         // ceil(2000/64)
#define CAND_CAP  8192
#define SORT_N    4096

// ---------------- device scratch (no allocations allowed) ----------------
__device__ unsigned int       g_hist1[4096];
__device__ unsigned int       g_hist2[4096];
__device__ unsigned int       g_b1;
__device__ unsigned int       g_above1;
__device__ unsigned int       g_thr24;
__device__ int                g_ccount;
__device__ unsigned long long g_cand[CAND_CAP];
__device__ int                g_order[PRE_TOPN];
__device__ float              g_score[PRE_TOPN];
__device__ float              g_bx[PRE_TOPN * 6];
__device__ float              g_vol[PRE_TOPN];
__device__ int                g_valid[PRE_TOPN];
__device__ unsigned long long g_mask[PRE_TOPN * MASK_COLS];
__device__ int                g_keep[POST_TOPN];
__device__ int                g_nk;

__device__ __forceinline__ unsigned int fkey(float f) {
    unsigned int b = __float_as_uint(f);
    return b ^ ((b & 0x80000000u) ? 0xFFFFFFFFu : 0x80000000u);
}

// ---------------- kernels ----------------

__global__ void k_clear() {
    int i = blockIdx.x * blockDim.x + threadIdx.x;
    if (i < 4096) { g_hist1[i] = 0u; g_hist2[i] = 0u; }
    if (i == 0) g_ccount = 0;
}

__global__ void k_hist1(const float* __restrict__ sc) {
    __shared__ unsigned int sh[4096];
    for (int i = threadIdx.x; i < 4096; i += blockDim.x) sh[i] = 0u;
    __syncthreads();
    for (int m = blockIdx.x * blockDim.x + threadIdx.x; m < N_SC;
         m += gridDim.x * blockDim.x) {
        unsigned int k = fkey(sc[m]);
        atomicAdd(&sh[k >> 20], 1u);
    }
    __syncthreads();
    for (int i = threadIdx.x; i < 4096; i += blockDim.x)
        if (sh[i]) atomicAdd(&g_hist1[i], sh[i]);
}

// Parallel suffix-threshold find over 4096 buckets (1 block, 1024 threads).
// Finds bucket b (from the TOP) s.t. count strictly above b < target <= count >= b.
__global__ void k_find1() {
    __shared__ unsigned int ps[1024];
    int tid = threadIdx.x;
    unsigned int v[4]; unsigned int s = 0;
#pragma unroll
    for (int k = 0; k < 4; k++) { v[k] = g_hist1[4095 - (tid * 4 + k)]; s += v[k]; }
    ps[tid] = s; __syncthreads();
    for (int off = 1; off < 1024; off <<= 1) {
        unsigned int x = ps[tid];
        unsigned int y = (tid >= off) ? ps[tid - off] : 0u;
        __syncthreads();
        ps[tid] = x + y;
        __syncthreads();
    }
    unsigned int incl = ps[tid];
    unsigned int excl = incl - s;
    const unsigned int target = PRE_TOPN;
    if (excl < target && incl >= target) {
        unsigned int cum = excl;
#pragma unroll
        for (int k = 0; k < 4; k++) {
            if (cum + v[k] >= target) {
                g_b1 = (unsigned int)(4095 - (tid * 4 + k));
                g_above1 = cum;
                break;
            }
            cum += v[k];
        }
    }
}

__global__ void k_hist2(const float* __restrict__ sc) {
    __shared__ unsigned int sh[4096];
    for (int i = threadIdx.x; i < 4096; i += blockDim.x) sh[i] = 0u;
    __syncthreads();
    unsigned int b1 = g_b1;
    for (int m = blockIdx.x * blockDim.x + threadIdx.x; m < N_SC;
         m += gridDim.x * blockDim.x) {
        unsigned int k = fkey(sc[m]);
        if ((k >> 20) == b1) atomicAdd(&sh[(k >> 8) & 0xFFFu], 1u);
    }
    __syncthreads();
    for (int i = threadIdx.x; i < 4096; i += blockDim.x)
        if (sh[i]) atomicAdd(&g_hist2[i], sh[i]);
}

__global__ void k_find2() {
    __shared__ unsigned int ps[1024];
    int tid = threadIdx.x;
    unsigned int v[4]; unsigned int s = 0;
#pragma unroll
    for (int k = 0; k < 4; k++) { v[k] = g_hist2[4095 - (tid * 4 + k)]; s += v[k]; }
    ps[tid] = s; __syncthreads();
    for (int off = 1; off < 1024; off <<= 1) {
        unsigned int x = ps[tid];
        unsigned int y = (tid >= off) ? ps[tid - off] : 0u;
        __syncthreads();
        ps[tid] = x + y;
        __syncthreads();
    }
    unsigned int incl = ps[tid];
    unsigned int excl = incl - s;
    unsigned int target = (unsigned int)PRE_TOPN - g_above1;
    if (excl < target && incl >= target) {
        unsigned int cum = excl;
#pragma unroll
        for (int k = 0; k < 4; k++) {
            if (cum + v[k] >= target) {
                unsigned int b2 = (unsigned int)(4095 - (tid * 4 + k));
                g_thr24 = (g_b1 << 12) | b2;
                break;
            }
            cum += v[k];
        }
    }
}

__global__ void k_gather(const float* __restrict__ sc) {
    unsigned int thr = g_thr24;
    for (int m = blockIdx.x * blockDim.x + threadIdx.x; m < N_SC;
         m += gridDim.x * blockDim.x) {
        unsigned int k = fkey(sc[m]);
        if ((k >> 8) >= thr) {
            int a = m >> 19;              // m / SHW  (SHW = 2^19)
            int shw = m & (SHW - 1);
            unsigned int r = (unsigned int)(shw * A_NUM + a);  // transposed flat idx
            int pos = atomicAdd(&g_ccount, 1);
            if (pos < CAND_CAP)
                g_cand[pos] = ((unsigned long long)k << 32) | (0xFFFFFFFFu - r);
        }
    }
}

// Bitonic sort of up to SORT_N composite keys, descending.  1 block, 1024 thr.
__global__ void k_sort() {
    __shared__ unsigned long long s[SORT_N];
    int tid = threadIdx.x;
    int cc = g_ccount; if (cc > CAND_CAP) cc = CAND_CAP; if (cc > SORT_N) cc = SORT_N;
    for (int i = tid; i < SORT_N; i += 1024) s[i] = (i < cc) ? g_cand[i] : 0ULL;
    __syncthreads();
    for (int k = 2; k <= SORT_N; k <<= 1) {
        for (int j = k >> 1; j > 0; j >>= 1) {
            for (int i = tid; i < SORT_N; i += 1024) {
                int ixj = i ^ j;
                if (ixj > i) {
                    bool down = ((i & k) == 0);   // descending overall
                    unsigned long long a = s[i], b = s[ixj];
                    bool sw = down ? (a < b) : (a > b);
                    if (sw) { s[i] = b; s[ixj] = a; }
                }
            }
            __syncthreads();
        }
    }
    for (int t = tid; t < PRE_TOPN; t += 1024) {
        unsigned long long v = s[t];
        unsigned int k = (unsigned int)(v >> 32);
        unsigned int r = 0xFFFFFFFFu - (unsigned int)(v & 0xFFFFFFFFu);
        g_order[t] = (int)r;
        unsigned int bits = (k & 0x80000000u) ? (k ^ 0x80000000u) : ~k;
        g_score[t] = __uint_as_float(bits);
    }
}

__global__ void k_boxes(const float* __restrict__ deltas,
                        const float* __restrict__ imi,
                        const float* __restrict__ anchors) {
    int i = blockIdx.x * blockDim.x + threadIdx.x;
    if (i >= PRE_TOPN) return;
    int r = g_order[i];
    int a = r % A_NUM;
    int shw = r / A_NUM;
    int w = shw & 127;
    int h = (shw >> 7) & 127;
    int sdepth = shw >> 14;
    float sx = (float)w * 4.0f, sy = (float)h * 4.0f, sz = (float)sdepth * 4.0f;
    float ax1 = sx + anchors[a * 6 + 0];
    float ay1 = sy + anchors[a * 6 + 1];
    float az1 = sz + anchors[a * 6 + 2];
    float ax2 = sx + anchors[a * 6 + 3];
    float ay2 = sy + anchors[a * 6 + 4];
    float az2 = sz + anchors[a * 6 + 5];
    float wA = ax2 - ax1 + 1.0f, hA = ay2 - ay1 + 1.0f, dA = az2 - az1 + 1.0f;
    float cx = ax1 + 0.5f * wA, cy = ay1 + 0.5f * hA, cz = az1 + 0.5f * dA;
    const float* dp = deltas + (size_t)(a * 6) * SHW + shw;
    float d0 = dp[0 * SHW], d1 = dp[1 * SHW], d2 = dp[2 * SHW];
    float d3 = dp[3 * SHW], d4 = dp[4 * SHW], d5 = dp[5 * SHW];
    float pcx = d0 * wA + cx, pcy = d1 * hA + cy, pcz = d2 * dA + cz;
    float pw = expf(d3) * wA, ph = expf(d4) * hA, pd = expf(d5) * dA;
    float slices = imi[0], height = imi[1], width = imi[2], scale = imi[3];
    float x1 = fminf(fmaxf(pcx - 0.5f * pw, 0.0f), width  - 1.0f);
    float y1 = fminf(fmaxf(pcy - 0.5f * ph, 0.0f), height - 1.0f);
    float z1 = fminf(fmaxf(pcz - 0.5f * pd, 0.0f), slices - 1.0f);
    float x2 = fminf(fmaxf(pcx + 0.5f * pw - 1.0f, 0.0f), width  - 1.0f);
    float y2 = fminf(fmaxf(pcy + 0.5f * ph - 1.0f, 0.0f), height - 1.0f);
    float z2 = fminf(fmaxf(pcz + 0.5f * pd - 1.0f, 0.0f), slices - 1.0f);
    g_bx[i * 6 + 0] = x1; g_bx[i * 6 + 1] = y1; g_bx[i * 6 + 2] = z1;
    g_bx[i * 6 + 3] = x2; g_bx[i * 6 + 4] = y2; g_bx[i * 6 + 5] = z2;
    g_vol[i] = (x2 - x1 + 1.0f) * (y2 - y1 + 1.0f) * (z2 - z1 + 1.0f);
    float ss = x2 - x1 + 1.0f;
    float xc = x1 + ss * 0.5f, yc = y1 + ss * 0.5f, zc = z1 + ss * 0.5f;
    g_valid[i] = (ss >= 8.0f * scale) && (xc < width) && (yc < height) && (zc < slices);
}

// Suppression mask: g_mask[i*32+cb] bit jj set iff j=cb*64+jj > i and iou(i,j) > T.
__global__ void k_mask() {
    int cb = blockIdx.x, rb = blockIdx.y;
    int t = threadIdx.x;               // 0..63
    int i = rb * 64 + t;
    if (cb < rb) {                      // all j < i: zero word (must still write!)
        if (i < PRE_TOPN) g_mask[i * MASK_COLS + cb] = 0ULL;
        return;
    }
    __shared__ float cbb[64][7];
    int j = cb * 64 + t;
    if (j < PRE_TOPN) {
#pragma unroll
        for (int q = 0; q < 6; q++) cbb[t][q] = g_bx[j * 6 + q];
        cbb[t][6] = g_vol[j];
    }
    __syncthreads();
    if (i >= PRE_TOPN) return;
    float x1 = g_bx[i * 6 + 0], y1 = g_bx[i * 6 + 1], z1 = g_bx[i * 6 + 2];
    float x2 = g_bx[i * 6 + 3], y2 = g_bx[i * 6 + 4], z2 = g_bx[i * 6 + 5];
    float vi = g_vol[i];
    unsigned long long word = 0ULL;
    int jn = min(64, PRE_TOPN - cb * 64);
    for (int jj = 0; jj < jn; jj++) {
        int jg = cb * 64 + jj;
        if (jg <= i) continue;
        float iw  = fminf(x2, cbb[jj][3]) - fmaxf(x1, cbb[jj][0]) + 1.0f;
        float ih  = fminf(y2, cbb[jj][4]) - fmaxf(y1, cbb[jj][1]) + 1.0f;
        float idd = fminf(z2, cbb[jj][5]) - fmaxf(z1, cbb[jj][2]) + 1.0f;
        iw = fmaxf(iw, 0.0f); ih = fmaxf(ih, 0.0f); idd = fmaxf(idd, 0.0f);
        float inter = iw * ih * idd;
        float iou = inter / (vi + cbb[jj][6] - inter);
        if (iou > NMS_T) word |= (1ULL << jj);
    }
    g_mask[i * MASK_COLS + cb] = word;
}

// Greedy sequential NMS scan.  One warp; lane l owns 64-bit word l of remv.
// Chunks of 64 rows staged through SMEM so the dependent chain is LDS-only.
__global__ void k_nms() {
    __shared__ unsigned long long sh[64 * MASK_COLS];   // 16KB
    int lane = threadIdx.x;                             // 0..31
    unsigned long long remv = 0ULL;
#pragma unroll 4
    for (int b = 0; b < 64; b++) {
        int jj = lane * 64 + b;
        if (jj >= PRE_TOPN || !g_valid[jj]) remv |= (1ULL << b);
    }
    int nk = 0;
    for (int c = 0; c < MASK_COLS && nk < POST_TOPN; c++) {
        int r0 = c * 64;
        int rn = min(64, PRE_TOPN - r0);
        for (int k = lane; k < rn * MASK_COLS; k += 32)
            sh[k] = g_mask[r0 * MASK_COLS + k];
        __syncwarp();
        unsigned long long cur = __shfl_sync(0xFFFFFFFFu, remv, c);
        for (int b = 0; b < rn && nk < POST_TOPN; b++) {
            if (!((cur >> b) & 1ULL)) {
                if (lane == 0) g_keep[nk] = r0 + b;
                nk++;
                cur  |= sh[b * MASK_COLS + c];
                remv |= sh[b * MASK_COLS + lane];
            }
        }
        __syncwarp();
    }
    if (lane == 0) g_nk = nk;
}

// Output layout (float32): rois 300x7 | scores 300 | keep_idx 300 | sel_valid 300
__global__ void k_out(float* __restrict__ out) {
    int p = blockIdx.x * blockDim.x + threadIdx.x;
    if (p >= POST_TOPN) return;
    int nk = g_nk;
    float* rois = out;
    float* sc   = out + POST_TOPN * 7;
    float* ki   = out + POST_TOPN * 7 + POST_TOPN;
    float* sv   = out + POST_TOPN * 7 + 2 * POST_TOPN;
    if (p < nk) {
        int i = g_keep[p];
        rois[p * 7 + 0] = 0.0f;
#pragma unroll
        for (int q = 0; q < 6; q++) rois[p * 7 + 1 + q] = g_bx[i * 6 + q];
        sc[p] = g_score[i];
        ki[p] = (float)g_order[i];
        sv[p] = 1.0f;
    } else {
#pragma unroll
        for (int q = 0; q < 7; q++) rois[p * 7 + q] = 0.0f;
        sc[p] = 0.0f;
        ki[p] = -1.0f;
        sv[p] = 0.0f;
    }
}

// ---------------- launch ----------------
extern "C" void kernel_launch(void* const* d_in, const int* in_sizes, int n_in,
                              void* d_out, int out_size) {
    const float* scores  = (const float*)d_in[0];   // (1,3,32,128,128)
    const float* deltas  = (const float*)d_in[1];   // (1,18,32,128,128)
    const float* im_info = (const float*)d_in[2];   // (1,4)
    const float* anchors = (const float*)d_in[3];   // (3,6)
    float* out = (float*)d_out;

    k_clear <<<8, 512>>>();
    k_hist1 <<<256, 256>>>(scores);
    k_find1 <<<1, 1024>>>();
    k_hist2 <<<256, 256>>>(scores);
    k_find2 <<<1, 1024>>>();
    k_gather<<<256, 256>>>(scores);
    k_sort  <<<1, 1024>>>();
    k_boxes <<<(PRE_TOPN + 255) / 256, 256>>>(deltas, im_info, anchors);
    k_mask  <<<dim3(MASK_COLS, 32), 64>>>();
    k_nms   <<<1, 32>>>();
    k_out   <<<1, 512>>>(out);
    (void)in_sizes; (void)n_in; (void)out_size;
}

// round 2
// speedup vs baseline: 1.1303x; 1.1303x over previous
#include <cuda_runtime.h>
#include <cuda_bf16.h>
#include <cstdint>

// Problem constants
#define A_NUM   3
#define S_DIM   32
#define H_DIM   128
#define W_DIM   128
#define SHW     (S_DIM * H_DIM * W_DIM)      // 524288 = 2^19
#define N_SC    (A_NUM * SHW)                // 1572864
#define N_SC4   (N_SC / 4)                   // 393216 float4
#define PRE_TOPN  2000
#define POST_TOPN 300
#define NMS_T     0.7f
#define MASK_COLS 32                         // ceil(2000/64)
#define CAND_CAP  8192

#define SCAN_BLOCKS 384
#define SCAN_THREADS 256
#define SCAN_STRIDE (SCAN_BLOCKS * SCAN_THREADS)   // 98304
#define SCAN_ITERS  (N_SC4 / SCAN_STRIDE)          // 4 exactly

// ---------------- device scratch (no allocations allowed) ----------------
__device__ unsigned int       g_hist1[4096];   // zero-init at load; find1 re-zeros
__device__ unsigned int       g_hist2[4096];   // find2 re-zeros
__device__ unsigned int       g_b1;
__device__ unsigned int       g_above1;
__device__ unsigned int       g_thr24;
__device__ int                g_ccount;       // find2 re-zeros before gather
__device__ unsigned long long g_cand[CAND_CAP];
__device__ int                g_order[PRE_TOPN];
__device__ float              g_score[PRE_TOPN];
__device__ float              g_bx[PRE_TOPN * 6];
__device__ float              g_vol[PRE_TOPN];
__device__ int                g_valid[PRE_TOPN];
__device__ unsigned long long g_mask[PRE_TOPN * MASK_COLS];

__device__ __forceinline__ unsigned int fkey(float f) {
    unsigned int b = __float_as_uint(f);
    return b ^ ((b & 0x80000000u) ? 0xFFFFFFFFu : 0x80000000u);
}

// ---------------- kernels ----------------

// Pass 1: 12-bit histogram of monotonic keys, warp-aggregated smem atomics.
__global__ void __launch_bounds__(SCAN_THREADS) k_hist1(const float4* __restrict__ sc4) {
    __shared__ unsigned int sh[4096];
    for (int i = threadIdx.x; i < 4096; i += SCAN_THREADS) sh[i] = 0u;
    __syncthreads();
    int t0 = blockIdx.x * SCAN_THREADS + threadIdx.x;
    float4 v[SCAN_ITERS];
#pragma unroll
    for (int it = 0; it < SCAN_ITERS; it++) v[it] = sc4[t0 + it * SCAN_STRIDE];
#pragma unroll
    for (int it = 0; it < SCAN_ITERS; it++) {
        float f[4] = {v[it].x, v[it].y, v[it].z, v[it].w};
#pragma unroll
        for (int j = 0; j < 4; j++) {
            unsigned int b = fkey(f[j]) >> 20;
            unsigned int m = __match_any_sync(0xFFFFFFFFu, b);
            if ((__ffs(m) - 1) == (int)(threadIdx.x & 31))
                atomicAdd(&sh[b], __popc(m));
        }
    }
    __syncthreads();
    for (int i = threadIdx.x; i < 4096; i += SCAN_THREADS)
        if (sh[i]) atomicAdd(&g_hist1[i], sh[i]);
}

// Find top-level bucket of the 2000th element; re-zero g_hist1 for next replay.
__global__ void k_find1() {
    __shared__ unsigned int ps[1024];
    int tid = threadIdx.x;
    unsigned int v[4]; unsigned int s = 0;
#pragma unroll
    for (int k = 0; k < 4; k++) {
        int b = 4095 - (tid * 4 + k);
        v[k] = g_hist1[b]; g_hist1[b] = 0u;           // consume + reset
        s += v[k];
    }
    ps[tid] = s; __syncthreads();
    for (int off = 1; off < 1024; off <<= 1) {
        unsigned int x = ps[tid];
        unsigned int y = (tid >= off) ? ps[tid - off] : 0u;
        __syncthreads();
        ps[tid] = x + y;
        __syncthreads();
    }
    unsigned int incl = ps[tid];
    unsigned int excl = incl - s;
    const unsigned int target = PRE_TOPN;
    if (excl < target && incl >= target) {
        unsigned int cum = excl;
#pragma unroll
        for (int k = 0; k < 4; k++) {
            if (cum + v[k] >= target) {
                g_b1 = (unsigned int)(4095 - (tid * 4 + k));
                g_above1 = cum;
                break;
            }
            cum += v[k];
        }
    }
}

// Pass 2: refine histogram on next 12 bits within bucket b1 (L2-resident read).
__global__ void __launch_bounds__(SCAN_THREADS) k_hist2(const float4* __restrict__ sc4) {
    __shared__ unsigned int sh[4096];
    for (int i = threadIdx.x; i < 4096; i += SCAN_THREADS) sh[i] = 0u;
    __syncthreads();
    unsigned int b1 = g_b1;
    int t0 = blockIdx.x * SCAN_THREADS + threadIdx.x;
    float4 v[SCAN_ITERS];
#pragma unroll
    for (int it = 0; it < SCAN_ITERS; it++) v[it] = sc4[t0 + it * SCAN_STRIDE];
#pragma unroll
    for (int it = 0; it < SCAN_ITERS; it++) {
        float f[4] = {v[it].x, v[it].y, v[it].z, v[it].w};
#pragma unroll
        for (int j = 0; j < 4; j++) {
            unsigned int k = fkey(f[j]);
            if ((k >> 20) == b1) atomicAdd(&sh[(k >> 8) & 0xFFFu], 1u);
        }
    }
    __syncthreads();
    for (int i = threadIdx.x; i < 4096; i += SCAN_THREADS)
        if (sh[i]) atomicAdd(&g_hist2[i], sh[i]);
}

// Find 24-bit threshold; re-zero g_hist2 and g_ccount for next stage/replay.
__global__ void k_find2() {
    __shared__ unsigned int ps[1024];
    int tid = threadIdx.x;
    if (tid == 0) g_ccount = 0;
    unsigned int v[4]; unsigned int s = 0;
#pragma unroll
    for (int k = 0; k < 4; k++) {
        int b = 4095 - (tid * 4 + k);
        v[k] = g_hist2[b]; g_hist2[b] = 0u;
        s += v[k];
    }
    ps[tid] = s; __syncthreads();
    for (int off = 1; off < 1024; off <<= 1) {
        unsigned int x = ps[tid];
        unsigned int y = (tid >= off) ? ps[tid - off] : 0u;
        __syncthreads();
        ps[tid] = x + y;
        __syncthreads();
    }
    unsigned int incl = ps[tid];
    unsigned int excl = incl - s;
    unsigned int target = (unsigned int)PRE_TOPN - g_above1;
    if (excl < target && incl >= target) {
        unsigned int cum = excl;
#pragma unroll
        for (int k = 0; k < 4; k++) {
            if (cum + v[k] >= target) {
                unsigned int b2 = (unsigned int)(4095 - (tid * 4 + k));
                g_thr24 = (g_b1 << 12) | b2;
                break;
            }
            cum += v[k];
        }
    }
}

// Pass 3: gather all candidates with key24 >= threshold (count >= 2000, ~2024).
__global__ void __launch_bounds__(SCAN_THREADS) k_gather(const float4* __restrict__ sc4) {
    unsigned int thr = g_thr24;
    int t0 = blockIdx.x * SCAN_THREADS + threadIdx.x;
    float4 v[SCAN_ITERS];
#pragma unroll
    for (int it = 0; it < SCAN_ITERS; it++) v[it] = sc4[t0 + it * SCAN_STRIDE];
#pragma unroll
    for (int it = 0; it < SCAN_ITERS; it++) {
        int base = (t0 + it * SCAN_STRIDE) * 4;
        float f[4] = {v[it].x, v[it].y, v[it].z, v[it].w};
#pragma unroll
        for (int j = 0; j < 4; j++) {
            unsigned int k = fkey(f[j]);
            if ((k >> 8) >= thr) {
                int m = base + j;
                int a = m >> 19;                 // m / SHW
                int shw = m & (SHW - 1);
                unsigned int r = (unsigned int)(shw * A_NUM + a);  // transposed idx
                int pos = atomicAdd(&g_ccount, 1);
                if (pos < CAND_CAP)
                    g_cand[pos] = ((unsigned long long)k << 32) | (0xFFFFFFFFu - r);
            }
        }
    }
}

// Rank candidates by composite key (exact, unique) and decode boxes for the
// top PRE_TOPN directly. rank < PRE_TOPN covers all 2000 slots exactly.
__global__ void __launch_bounds__(256) k_rank(const float* __restrict__ deltas,
                                              const float* __restrict__ imi,
                                              const float* __restrict__ anchors) {
    __shared__ unsigned long long s[2048];
    int cc = g_ccount; if (cc > CAND_CAP) cc = CAND_CAP;
    int gtid = blockIdx.x * 256 + threadIdx.x;           // 0..4095
    int outer = (cc + 4095) / 4096;
    for (int o = 0; o < outer; o++) {
        int t = o * 4096 + gtid;
        unsigned long long myk = (t < cc) ? g_cand[t] : 0ULL;
        int rank = 0;
        for (int base = 0; base < cc; base += 2048) {
            int n = min(2048, cc - base);
            for (int j = threadIdx.x; j < n; j += 256) s[j] = g_cand[base + j];
            __syncthreads();
            if (t < cc)
                for (int j = 0; j < n; j++) rank += (s[j] > myk);
            __syncthreads();
        }
        if (t < cc && rank < PRE_TOPN) {
            unsigned int k = (unsigned int)(myk >> 32);
            unsigned int r = 0xFFFFFFFFu - (unsigned int)(myk & 0xFFFFFFFFu);
            g_order[rank] = (int)r;
            unsigned int bits = (k & 0x80000000u) ? (k ^ 0x80000000u) : ~k;
            g_score[rank] = __uint_as_float(bits);
            // --- box decode ---
            int a = (int)(r % A_NUM);
            int shw = (int)(r / A_NUM);
            int w = shw & 127;
            int h = (shw >> 7) & 127;
            int sd = shw >> 14;
            float sx = (float)w * 4.0f, sy = (float)h * 4.0f, sz = (float)sd * 4.0f;
            float ax1 = sx + anchors[a * 6 + 0];
            float ay1 = sy + anchors[a * 6 + 1];
            float az1 = sz + anchors[a * 6 + 2];
            float ax2 = sx + anchors[a * 6 + 3];
            float ay2 = sy + anchors[a * 6 + 4];
            float az2 = sz + anchors[a * 6 + 5];
            float wA = ax2 - ax1 + 1.0f, hA = ay2 - ay1 + 1.0f, dA = az2 - az1 + 1.0f;
            float cx = ax1 + 0.5f * wA, cy = ay1 + 0.5f * hA, cz = az1 + 0.5f * dA;
            const float* dp = deltas + (size_t)(a * 6) * SHW + shw;
            float d0 = dp[0 * SHW], d1 = dp[1 * SHW], d2 = dp[2 * SHW];
            float d3 = dp[3 * SHW], d4 = dp[4 * SHW], d5 = dp[5 * SHW];
            float pcx = d0 * wA + cx, pcy = d1 * hA + cy, pcz = d2 * dA + cz;
            float pw = expf(d3) * wA, ph = expf(d4) * hA, pd = expf(d5) * dA;
            float slices = imi[0], height = imi[1], width = imi[2], scale = imi[3];
            float x1 = fminf(fmaxf(pcx - 0.5f * pw, 0.0f), width  - 1.0f);
            float y1 = fminf(fmaxf(pcy - 0.5f * ph, 0.0f), height - 1.0f);
            float z1 = fminf(fmaxf(pcz - 0.5f * pd, 0.0f), slices - 1.0f);
            float x2 = fminf(fmaxf(pcx + 0.5f * pw - 1.0f, 0.0f), width  - 1.0f);
            float y2 = fminf(fmaxf(pcy + 0.5f * ph - 1.0f, 0.0f), height - 1.0f);
            float z2 = fminf(fmaxf(pcz + 0.5f * pd - 1.0f, 0.0f), slices - 1.0f);
            g_bx[rank * 6 + 0] = x1; g_bx[rank * 6 + 1] = y1; g_bx[rank * 6 + 2] = z1;
            g_bx[rank * 6 + 3] = x2; g_bx[rank * 6 + 4] = y2; g_bx[rank * 6 + 5] = z2;
            g_vol[rank] = (x2 - x1 + 1.0f) * (y2 - y1 + 1.0f) * (z2 - z1 + 1.0f);
            float ss = x2 - x1 + 1.0f;
            float xc = x1 + ss * 0.5f, yc = y1 + ss * 0.5f, zc = z1 + ss * 0.5f;
            g_valid[rank] = (ss >= 8.0f * scale) && (xc < width) && (yc < height) && (zc < slices);
        }
    }
}

// Suppression mask: g_mask[i*32+cb] bit jj set iff j=cb*64+jj > i and iou(i,j) > T.
__global__ void k_mask() {
    int cb = blockIdx.x, rb = blockIdx.y;
    int t = threadIdx.x;               // 0..63
    int i = rb * 64 + t;
    if (cb < rb) {                      // all j < i: zero word (must still write!)
        if (i < PRE_TOPN) g_mask[i * MASK_COLS + cb] = 0ULL;
        return;
    }
    __shared__ float cbb[64][7];
    int j = cb * 64 + t;
    if (j < PRE_TOPN) {
#pragma unroll
        for (int q = 0; q < 6; q++) cbb[t][q] = g_bx[j * 6 + q];
        cbb[t][6] = g_vol[j];
    }
    __syncthreads();
    if (i >= PRE_TOPN) return;
    float x1 = g_bx[i * 6 + 0], y1 = g_bx[i * 6 + 1], z1 = g_bx[i * 6 + 2];
    float x2 = g_bx[i * 6 + 3], y2 = g_bx[i * 6 + 4], z2 = g_bx[i * 6 + 5];
    float vi = g_vol[i];
    unsigned long long word = 0ULL;
    int jn = min(64, PRE_TOPN - cb * 64);
    for (int jj = 0; jj < jn; jj++) {
        int jg = cb * 64 + jj;
        if (jg <= i) continue;
        float iw  = fminf(x2, cbb[jj][3]) - fmaxf(x1, cbb[jj][0]) + 1.0f;
        float ih  = fminf(y2, cbb[jj][4]) - fmaxf(y1, cbb[jj][1]) + 1.0f;
        float idd = fminf(z2, cbb[jj][5]) - fmaxf(z1, cbb[jj][2]) + 1.0f;
        iw = fmaxf(iw, 0.0f); ih = fmaxf(ih, 0.0f); idd = fmaxf(idd, 0.0f);
        float inter = iw * ih * idd;
        float iou = inter / (vi + cbb[jj][6] - inter);
        if (iou > NMS_T) word |= (1ULL << jj);
    }
    g_mask[i * MASK_COLS + cb] = word;
}

// Greedy sequential NMS (warp 0) with double-buffered chunk prefetch
// (threads 32..127), fused output stage. 1 block x 128 threads.
__global__ void __launch_bounds__(128) k_nms_out(float* __restrict__ out) {
    __shared__ unsigned long long buf[2][64 * MASK_COLS];   // 2 x 16KB
    __shared__ int keep_s[POST_TOPN];
    __shared__ int snk;
    __shared__ int sflag;
    int tid = threadIdx.x;
    int lane = tid & 31;

    if (tid == 0) { sflag = 0; snk = 0; }
    // stage chunk 0 (all 128 threads)
    for (int k = tid; k < 64 * MASK_COLS; k += 128) buf[0][k] = g_mask[k];

    unsigned long long remv = 0ULL;
    if (tid < 32) {
#pragma unroll 4
        for (int b = 0; b < 64; b++) {
            int jj = lane * 64 + b;
            if (jj >= PRE_TOPN || !g_valid[jj]) remv |= (1ULL << b);
        }
    }
    __syncthreads();

    int nk = 0;
    for (int c = 0; c < MASK_COLS; c++) {
        // prefetch next chunk (warps 1-3) while warp 0 scans current
        if (tid >= 32 && c + 1 < MASK_COLS) {
            int r0n = (c + 1) * 64;
            int rnn = min(64, PRE_TOPN - r0n);
            for (int k = tid - 32; k < rnn * MASK_COLS; k += 96)
                buf[(c + 1) & 1][k] = g_mask[r0n * MASK_COLS + k];
        }
        if (tid < 32) {
            const unsigned long long* sb = buf[c & 1];
            int r0 = c * 64;
            int rn = min(64, PRE_TOPN - r0);
            unsigned long long cur = __shfl_sync(0xFFFFFFFFu, remv, c);
            for (int b = 0; b < rn && nk < POST_TOPN; b++) {
                if (!((cur >> b) & 1ULL)) {
                    if (lane == 0) keep_s[nk] = r0 + b;
                    nk++;
                    cur  |= sb[b * MASK_COLS + c];
                    remv |= sb[b * MASK_COLS + lane];
                }
            }
            if (lane == 0 && (nk >= POST_TOPN || c == MASK_COLS - 1)) {
                snk = nk; sflag = 1;
            }
        }
        __syncthreads();
        if (sflag) break;
    }

    // fused output: rois 300x7 | scores 300 | keep_idx 300 | sel_valid 300
    int nkf = snk;
    float* rois = out;
    float* sc   = out + POST_TOPN * 7;
    float* ki   = out + POST_TOPN * 7 + POST_TOPN;
    float* sv   = out + POST_TOPN * 7 + 2 * POST_TOPN;
    for (int p = tid; p < POST_TOPN; p += 128) {
        if (p < nkf) {
            int i = keep_s[p];
            rois[p * 7 + 0] = 0.0f;
#pragma unroll
            for (int q = 0; q < 6; q++) rois[p * 7 + 1 + q] = g_bx[i * 6 + q];
            sc[p] = g_score[i];
            ki[p] = (float)g_order[i];
            sv[p] = 1.0f;
        } else {
#pragma unroll
            for (int q = 0; q < 7; q++) rois[p * 7 + q] = 0.0f;
            sc[p] = 0.0f;
            ki[p] = -1.0f;
            sv[p] = 0.0f;
        }
    }
}

// ---------------- launch ----------------
extern "C" void kernel_launch(void* const* d_in, const int* in_sizes, int n_in,
                              void* d_out, int out_size) {
    const float4* scores = (const float4*)d_in[0];  // (1,3,32,128,128)
    const float* deltas  = (const float*)d_in[1];   // (1,18,32,128,128)
    const float* im_info = (const float*)d_in[2];   // (1,4)
    const float* anchors = (const float*)d_in[3];   // (3,6)
    float* out = (float*)d_out;

    k_hist1 <<<SCAN_BLOCKS, SCAN_THREADS>>>(scores);
    k_find1 <<<1, 1024>>>();
    k_hist2 <<<SCAN_BLOCKS, SCAN_THREADS>>>(scores);
    k_find2 <<<1, 1024>>>();
    k_gather<<<SCAN_BLOCKS, SCAN_THREADS>>>(scores);
    k_rank  <<<16, 256>>>(deltas, im_info, anchors);
    k_mask  <<<dim3(MASK_COLS, 32), 64>>>();
    k_nms_out<<<1, 128>>>(out);
    (void)in_sizes; (void)n_in; (void)out_size;
}

// round 3
// speedup vs baseline: 1.2408x; 1.0978x over previous
#include <cuda_runtime.h>
#include <cuda_bf16.h>
#include <cstdint>

typedef unsigned int u32;
typedef unsigned long long u64;

#define A_NUM   3
#define SHW     (32 * 128 * 128)
#define N_SC    (A_NUM * SHW)
#define N_SC4   (N_SC / 4)
#define PRE_TOPN  2000
#define POST_TOPN 300
#define NMS_T     0.7f
#define MASK_COLS 32
#define CAND_CAP  8192

#define NBLK 148
#define NTHR 256
#define GSTRIDE (NBLK * NTHR)

__device__ u32  g_hist1[4096];
__device__ u32  g_hist2[4096];
__device__ u32  g_b1, g_above1, g_thr24;
__device__ int  g_ccount;
__device__ u64  g_cand[CAND_CAP];
__device__ int  g_order[PRE_TOPN];
__device__ float g_score[PRE_TOPN];
__device__ float g_bx[PRE_TOPN * 6];
__device__ float g_vol[PRE_TOPN];
__device__ u64  g_invalid[32];
__device__ u64  g_mask[PRE_TOPN * MASK_COLS];
__device__ u32  g_barc;
__device__ u32  g_barg;

__device__ __forceinline__ u32 fkey(float f) {
    u32 b = __float_as_uint(f);
    return b ^ ((b & 0x80000000u) ? 0xFFFFFFFFu : 0x80000000u);
}

__device__ __forceinline__ void gbar() {
    __syncthreads();
    if (threadIdx.x == 0) {
        u32 gen = *((volatile u32*)&g_barg);
        __threadfence();
        if (atomicAdd(&g_barc, 1u) == NBLK - 1) {
            g_barc = 0;
            __threadfence();
            atomicExch(&g_barg, gen + 1);
        } else {
            while (*((volatile u32*)&g_barg) == gen) __nanosleep(64);
        }
        __threadfence();
    }
    __syncthreads();
}

// Block-0: find bucket containing the `target`-th element from the top of a
// 4096-bucket histogram (zeroing it), then write stage-specific results.
// stage=1: writes g_b1, g_above1.  stage=2: writes g_thr24 = (g_b1<<12)|b.
__device__ __forceinline__ void find_bucket(u32* hist, u32 target, int stage, u32* ws) {
    int tid = threadIdx.x, lane = tid & 31, wid = tid >> 5;
    int base = 4095 - tid * 16;
    u32 v[16]; u32 s = 0;
#pragma unroll
    for (int k = 0; k < 16; k++) {
        u32 h = hist[base - k]; hist[base - k] = 0u;
        v[k] = h; s += h;
    }
    u32 x = s;
#pragma unroll
    for (int off = 1; off < 32; off <<= 1) {
        u32 y = __shfl_up_sync(0xFFFFFFFFu, x, off);
        if (lane >= off) x += y;
    }
    if (lane == 31) ws[wid] = x;
    __syncthreads();
    if (tid == 0) {
        u32 acc = 0;
#pragma unroll
        for (int w = 0; w < 8; w++) { u32 t2 = ws[w]; ws[w] = acc; acc += t2; }
    }
    __syncthreads();
    u32 incl = x + ws[wid];
    u32 excl = incl - s;
    if (excl < target && incl >= target) {
        u32 cum = excl;
#pragma unroll
        for (int k = 0; k < 16; k++) {
            if (cum + v[k] >= target) {
                if (stage == 1) { g_b1 = (u32)(base - k); g_above1 = cum; }
                else            { g_thr24 = (g_b1 << 12) | (u32)(base - k); }
                break;
            }
            cum += v[k];
        }
    }
    __syncthreads();
}

#define SM_BYTES 34048
__global__ void __launch_bounds__(NTHR, 1)
k_all(const float4* __restrict__ sc4, const float* __restrict__ deltas,
      const float* __restrict__ imi, const float* __restrict__ anchors,
      float* __restrict__ out) {
    __shared__ __align__(16) char smraw[SM_BYTES];
    __shared__ u32 ws[8];
    const int tid = threadIdx.x;
    const int bid = blockIdx.x;
    const int lane = tid & 31;

    // ---------- Phase 1: coarse 12-bit histogram ----------
    {
        u32* sh = (u32*)smraw;
        for (int i = tid; i < 4096; i += NTHR) sh[i] = 0u;
        __syncthreads();
#pragma unroll 4
        for (int i = bid * NTHR + tid; i < N_SC4; i += GSTRIDE) {
            float4 v = sc4[i];
            float f[4] = {v.x, v.y, v.z, v.w};
#pragma unroll
            for (int j = 0; j < 4; j++) {
                u32 b = fkey(f[j]) >> 20;
                u32 m = __match_any_sync(0xFFFFFFFFu, b);
                if ((__ffs(m) - 1) == lane) atomicAdd(&sh[b], __popc(m));
            }
        }
        __syncthreads();
        for (int i = tid; i < 4096; i += NTHR)
            if (sh[i]) atomicAdd(&g_hist1[i], sh[i]);
    }
    gbar();

    // ---------- Phase 2: find coarse bucket ----------
    if (bid == 0) find_bucket(g_hist1, PRE_TOPN, 1, ws);
    gbar();

    // ---------- Phase 3: refine histogram ----------
    {
        u32* sh = (u32*)smraw;
        for (int i = tid; i < 4096; i += NTHR) sh[i] = 0u;
        __syncthreads();
        u32 b1 = g_b1;
#pragma unroll 4
        for (int i = bid * NTHR + tid; i < N_SC4; i += GSTRIDE) {
            float4 v = sc4[i];
            float f[4] = {v.x, v.y, v.z, v.w};
#pragma unroll
            for (int j = 0; j < 4; j++) {
                u32 k = fkey(f[j]);
                if ((k >> 20) == b1) atomicAdd(&sh[(k >> 8) & 0xFFFu], 1u);
            }
        }
        __syncthreads();
        for (int i = tid; i < 4096; i += NTHR)
            if (sh[i]) atomicAdd(&g_hist2[i], sh[i]);
    }
    gbar();

    // ---------- Phase 4: find 24-bit threshold; reset state ----------
    if (bid == 0) {
        if (tid == 0) g_ccount = 0;
        if (tid < 32) g_invalid[tid] = (tid == 31) ? 0xFFFFFFFFFFFF0000ULL : 0ULL;
        __syncthreads();
        find_bucket(g_hist2, PRE_TOPN - g_above1, 2, ws);
    }
    gbar();

    // ---------- Phase 5: gather candidates ----------
    {
        u32 thr = g_thr24;
#pragma unroll 4
        for (int i = bid * NTHR + tid; i < N_SC4; i += GSTRIDE) {
            float4 v = sc4[i];
            int base = i * 4;
            float f[4] = {v.x, v.y, v.z, v.w};
#pragma unroll
            for (int j = 0; j < 4; j++) {
                u32 k = fkey(f[j]);
                bool pred = ((k >> 8) >= thr);
                u32 bal = __ballot_sync(0xFFFFFFFFu, pred);
                if (bal) {
                    int leader = __ffs(bal) - 1;
                    int posb = 0;
                    if (lane == leader) posb = atomicAdd(&g_ccount, __popc(bal));
                    posb = __shfl_sync(0xFFFFFFFFu, posb, leader);
                    if (pred) {
                        int m = base + j;
                        int a = m >> 19;
                        int shw = m & (SHW - 1);
                        u32 r = (u32)(shw * A_NUM + a);
                        int pos = posb + __popc(bal & ((1u << lane) - 1u));
                        if (pos < CAND_CAP)
                            g_cand[pos] = ((u64)k << 32) | (0xFFFFFFFFu - r);
                    }
                }
            }
        }
    }
    gbar();

    // ---------- Phase 6: rank + decode; idle blocks zero g_mask ----------
    {
        int cc = g_ccount; if (cc > CAND_CAP) cc = CAND_CAP;
        int bact = (cc + NTHR - 1) / NTHR;
        if (bid < bact) {
            u64* st = (u64*)smraw;
            int t = bid * NTHR + tid;
            u64 myk = (t < cc) ? g_cand[t] : 0ULL;
            int rank = 0;
            for (int b0 = 0; b0 < cc; b0 += 2048) {
                int n = min(2048, cc - b0);
                for (int j = tid; j < n; j += NTHR) st[j] = g_cand[b0 + j];
                __syncthreads();
                if (t < cc)
                    for (int j = 0; j < n; j++) rank += (st[j] > myk);
                __syncthreads();
            }
            if (t < cc && rank < PRE_TOPN) {
                u32 k = (u32)(myk >> 32);
                u32 r = 0xFFFFFFFFu - (u32)(myk & 0xFFFFFFFFu);
                g_order[rank] = (int)r;
                u32 bits = (k & 0x80000000u) ? (k ^ 0x80000000u) : ~k;
                g_score[rank] = __uint_as_float(bits);
                int a   = (int)(r % A_NUM);
                int shw = (int)(r / A_NUM);
                int w = shw & 127, h = (shw >> 7) & 127, sd = shw >> 14;
                float sx = (float)w * 4.0f, sy = (float)h * 4.0f, sz = (float)sd * 4.0f;
                float ax1 = sx + anchors[a * 6 + 0];
                float ay1 = sy + anchors[a * 6 + 1];
                float az1 = sz + anchors[a * 6 + 2];
                float ax2 = sx + anchors[a * 6 + 3];
                float ay2 = sy + anchors[a * 6 + 4];
                float az2 = sz + anchors[a * 6 + 5];
                float wA = ax2 - ax1 + 1.0f, hA = ay2 - ay1 + 1.0f, dA = az2 - az1 + 1.0f;
                float cx = ax1 + 0.5f * wA, cy = ay1 + 0.5f * hA, cz = az1 + 0.5f * dA;
                const float* dp = deltas + (size_t)(a * 6) * SHW + shw;
                float d0 = dp[0 * SHW], d1 = dp[1 * SHW], d2 = dp[2 * SHW];
                float d3 = dp[3 * SHW], d4 = dp[4 * SHW], d5 = dp[5 * SHW];
                float pcx = d0 * wA + cx, pcy = d1 * hA + cy, pcz = d2 * dA + cz;
                float pw = expf(d3) * wA, ph = expf(d4) * hA, pd = expf(d5) * dA;
                float slices = imi[0], height = imi[1], width = imi[2], scale = imi[3];
                float x1 = fminf(fmaxf(pcx - 0.5f * pw, 0.0f), width  - 1.0f);
                float y1 = fminf(fmaxf(pcy - 0.5f * ph, 0.0f), height - 1.0f);
                float z1 = fminf(fmaxf(pcz - 0.5f * pd, 0.0f), slices - 1.0f);
                float x2 = fminf(fmaxf(pcx + 0.5f * pw - 1.0f, 0.0f), width  - 1.0f);
                float y2 = fminf(fmaxf(pcy + 0.5f * ph - 1.0f, 0.0f), height - 1.0f);
                float z2 = fminf(fmaxf(pcz + 0.5f * pd - 1.0f, 0.0f), slices - 1.0f);
                g_bx[rank * 6 + 0] = x1; g_bx[rank * 6 + 1] = y1; g_bx[rank * 6 + 2] = z1;
                g_bx[rank * 6 + 3] = x2; g_bx[rank * 6 + 4] = y2; g_bx[rank * 6 + 5] = z2;
                g_vol[rank] = (x2 - x1 + 1.0f) * (y2 - y1 + 1.0f) * (z2 - z1 + 1.0f);
                float ss = x2 - x1 + 1.0f;
                float xc = x1 + ss * 0.5f, yc = y1 + ss * 0.5f, zc = z1 + ss * 0.5f;
                bool valid = (ss >= 8.0f * scale) && (xc < width) && (yc < height) && (zc < slices);
                if (!valid) atomicOr(&g_invalid[rank >> 6], 1ULL << (rank & 63));
            }
        } else {
            int zb = bid - bact;
            int nzb = NBLK - bact;
            for (int k = zb * NTHR + tid; k < PRE_TOPN * MASK_COLS; k += nzb * NTHR)
                g_mask[k] = 0ULL;
        }
    }
    gbar();

    // ---------- Phase 7: IoU suppression masks (upper-triangle tiles) ----
    {
        float* cb4 = (float*)smraw;
        int grp = tid >> 6, lt = tid & 63;
        for (int base = bid * 4; base < 1024; base += NBLK * 4) {
            int tile = base + grp;
            int rb = tile >> 5, cbi = tile & 31;
            bool act = (tile < 1024) && (cbi >= rb);
            float* cbb = cb4 + grp * 64 * 7;
            if (act) {
                int j = cbi * 64 + lt;
                if (j < PRE_TOPN) {
#pragma unroll
                    for (int q = 0; q < 6; q++) cbb[lt * 7 + q] = g_bx[j * 6 + q];
                    cbb[lt * 7 + 6] = g_vol[j];
                }
            }
            __syncthreads();
            if (act) {
                int i = rb * 64 + lt;
                if (i < PRE_TOPN) {
                    float x1 = g_bx[i * 6 + 0], y1 = g_bx[i * 6 + 1], z1 = g_bx[i * 6 + 2];
                    float x2 = g_bx[i * 6 + 3], y2 = g_bx[i * 6 + 4], z2 = g_bx[i * 6 + 5];
                    float vi = g_vol[i];
                    u64 word = 0ULL;
                    int jn = min(64, PRE_TOPN - cbi * 64);
                    for (int jj = 0; jj < jn; jj++) {
                        int jg = cbi * 64 + jj;
                        if (jg <= i) continue;
                        const float* cj = cbb + jj * 7;
                        float iw  = fminf(x2, cj[3]) - fmaxf(x1, cj[0]) + 1.0f;
                        float ih  = fminf(y2, cj[4]) - fmaxf(y1, cj[1]) + 1.0f;
                        float idd = fminf(z2, cj[5]) - fmaxf(z1, cj[2]) + 1.0f;
                        iw = fmaxf(iw, 0.0f); ih = fmaxf(ih, 0.0f); idd = fmaxf(idd, 0.0f);
                        float inter = iw * ih * idd;
                        float iou = inter / (vi + cj[6] - inter);
                        if (iou > NMS_T) word |= (1ULL << jj);
                    }
                    g_mask[i * MASK_COLS + cbi] = word;
                }
            }
            __syncthreads();
        }
    }
    gbar();

    // ---------- Phase 8: greedy NMS + output (block 0) ----------
    if (bid != 0) return;
    {
        u64* buf    = (u64*)smraw;
        int* keep_s = (int*)(smraw + 32768);
        int* s_nk   = (int*)(smraw + 32768 + 1200);
        int* s_flag = (int*)(smraw + 32768 + 1204);
        if (tid == 0) { *s_flag = 0; *s_nk = 0; }
        u64 remv = 0ULL;
        if (tid < 32) remv = g_invalid[tid];
        for (int k = tid; k < 64 * MASK_COLS; k += NTHR) buf[k] = g_mask[k];
        __syncthreads();

        int nk = 0;
        for (int c = 0; c < MASK_COLS; c++) {
            if (tid >= 32 && c + 1 < MASK_COLS) {
                int r0n = (c + 1) * 64;
                int rnn = min(64, PRE_TOPN - r0n);
                u64* dst = buf + ((c + 1) & 1) * 2048;
                for (int k = tid - 32; k < rnn * MASK_COLS; k += (NTHR - 32))
                    dst[k] = g_mask[r0n * MASK_COLS + k];
            }
            if (tid < 32) {
                const u64* sb = buf + (c & 1) * 2048;
                u64 cur = __shfl_sync(0xFFFFFFFFu, remv, c);
                u64 pend = ~cur;
                while (pend && nk < POST_TOPN) {
                    int b = __ffsll((long long)pend) - 1;
                    if (tid == 0) keep_s[nk] = c * 64 + b;
                    nk++;
                    u64 m  = sb[b * MASK_COLS + tid];
                    u64 mc = sb[b * MASK_COLS + c];
                    remv |= m;
                    pend &= ~mc;
                    pend &= ~(1ULL << b);
                }
                if (tid == 0 && (nk >= POST_TOPN || c == MASK_COLS - 1)) {
                    *s_nk = nk; *s_flag = 1;
                }
            }
            __syncthreads();
            if (*s_flag) break;
        }

        int nkf = *s_nk;
        float* rois = out;
        float* sc   = out + POST_TOPN * 7;
        float* ki   = out + POST_TOPN * 7 + POST_TOPN;
        float* sv   = out + POST_TOPN * 7 + 2 * POST_TOPN;
        for (int p = tid; p < POST_TOPN; p += NTHR) {
            if (p < nkf) {
                int i = keep_s[p];
                rois[p * 7 + 0] = 0.0f;
#pragma unroll
                for (int q = 0; q < 6; q++) rois[p * 7 + 1 + q] = g_bx[i * 6 + q];
                sc[p] = g_score[i];
                ki[p] = (float)g_order[i];
                sv[p] = 1.0f;
            } else {
#pragma unroll
                for (int q = 0; q < 7; q++) rois[p * 7 + q] = 0.0f;
                sc[p] = 0.0f;
                ki[p] = -1.0f;
                sv[p] = 0.0f;
            }
        }
    }
}

extern "C" void kernel_launch(void* const* d_in, const int* in_sizes, int n_in,
                              void* d_out, int out_size) {
    const float4* scores = (const float4*)d_in[0];
    const float*  deltas = (const float*)d_in[1];
    const float*  im_info = (const float*)d_in[2];
    const float*  anchors = (const float*)d_in[3];
    float* out = (float*)d_out;
    k_all<<<NBLK, NTHR>>>(scores, deltas, im_info, anchors, out);
    (void)in_sizes; (void)n_in; (void)out_size;
}